// round 2
// baseline (speedup 1.0000x reference)
#include <cuda_runtime.h>
#include <cuda_bf16.h>
#include <cstdint>

// MinimalThinkingRefiner: out = x + alpha*(x*scale + shift) where mask[row]==2, else x.
// Persistent grid-stride streaming kernel: no wave transitions, MLP via unroll-4.

__global__ void __launch_bounds__(256, 8)
refiner_persistent(const float4* __restrict__ x,
                   const int*    __restrict__ mask,
                   const float4* __restrict__ scale,
                   const float4* __restrict__ shift,
                   const float*  __restrict__ alpha_p,
                   float4* __restrict__ out,
                   long n4, int hshift, int hv)
{
    const float a = __ldg(alpha_p);
    const long stride = (long)gridDim.x * blockDim.x;

    #pragma unroll 4
    for (long i = (long)blockIdx.x * blockDim.x + threadIdx.x; i < n4; i += stride) {
        const int row = (hshift >= 0) ? (int)(i >> hshift) : (int)(i / hv);
        float4 v = __ldcs(&x[i]);
        if (__ldg(&mask[row]) == 2) {            // warp-uniform: hv % 32 == 0
            const int h = (hshift >= 0) ? (int)(i & (hv - 1)) : (int)(i % hv);
            const float4 s = __ldg(&scale[h]);
            const float4 t = __ldg(&shift[h]);
            v.x = fmaf(a, fmaf(v.x, s.x, t.x), v.x);
            v.y = fmaf(a, fmaf(v.y, s.y, t.y), v.y);
            v.z = fmaf(a, fmaf(v.z, s.z, t.z), v.z);
            v.w = fmaf(a, fmaf(v.w, s.w, t.w), v.w);
        }
        __stcs(&out[i], v);
    }
}

extern "C" void kernel_launch(void* const* d_in, const int* in_sizes, int n_in,
                              void* d_out, int out_size)
{
    const float* x     = (const float*)d_in[0];   // [B,S,H]
    const int*   mask  = (const int*)d_in[1];     // [B,S]
    const float* scale = (const float*)d_in[2];   // [H]
    const float* shift = (const float*)d_in[3];   // [H]
    const float* alpha = (const float*)d_in[4];   // scalar

    const int rows = in_sizes[1];                 // B*S
    const int H    = in_sizes[0] / rows;          // 4096
    const int hv   = H / 4;                       // float4 per row (1024)
    const long n4  = (long)rows * hv;

    // hshift = log2(hv) if hv is a power of two, else -1 (fallback to division)
    int hshift = -1;
    if ((hv & (hv - 1)) == 0) {
        hshift = 0;
        while ((1 << hshift) != hv) hshift++;
    }

    int sms = 148;
    cudaDeviceGetAttribute(&sms, cudaDevAttrMultiProcessorCount, 0);
    const int grid = sms * 8;                     // persistent: one wave

    refiner_persistent<<<grid, 256>>>(
        (const float4*)x, mask, (const float4*)scale, (const float4*)shift,
        alpha, (float4*)d_out, n4, hshift, hv);
}

// round 3
// speedup vs baseline: 1.0608x; 1.0608x over previous
#include <cuda_runtime.h>
#include <cuda_bf16.h>
#include <cstdint>

// MinimalThinkingRefiner: out = x + alpha*(x*scale + shift) where mask[row]==2, else x.
// One CTA per row, float4 vectorized. Loads use default policy (let x linger in L2
// across graph replays); stores are evict-first (out is never read -> don't pollute L2).

__global__ void __launch_bounds__(256, 8)
refiner_kernel(const float4* __restrict__ x,
               const int*    __restrict__ mask,
               const float4* __restrict__ scale,
               const float4* __restrict__ shift,
               const float*  __restrict__ alpha_p,
               float4* __restrict__ out,
               int hv /* H/4 */)
{
    const int row = blockIdx.x;
    const bool thinking = (mask[row] == 2);
    const size_t base = (size_t)row * hv;
    const float4* __restrict__ xr = x + base;
    float4* __restrict__ orow = out + base;

    if (!thinking) {
        // pure streaming copy
        #pragma unroll 4
        for (int i = threadIdx.x; i < hv; i += blockDim.x) {
            float4 v = xr[i];
            __stcs(&orow[i], v);
        }
    } else {
        const float a = __ldg(alpha_p);
        #pragma unroll 2
        for (int i = threadIdx.x; i < hv; i += blockDim.x) {
            float4 v = xr[i];
            float4 s = scale[i];
            float4 t = shift[i];
            v.x = fmaf(a, fmaf(v.x, s.x, t.x), v.x);
            v.y = fmaf(a, fmaf(v.y, s.y, t.y), v.y);
            v.z = fmaf(a, fmaf(v.z, s.z, t.z), v.z);
            v.w = fmaf(a, fmaf(v.w, s.w, t.w), v.w);
            __stcs(&orow[i], v);
        }
    }
}

extern "C" void kernel_launch(void* const* d_in, const int* in_sizes, int n_in,
                              void* d_out, int out_size)
{
    const float* x     = (const float*)d_in[0];   // [B,S,H]
    const int*   mask  = (const int*)d_in[1];     // [B,S]
    const float* scale = (const float*)d_in[2];   // [H]
    const float* shift = (const float*)d_in[3];   // [H]
    const float* alpha = (const float*)d_in[4];   // scalar

    const int rows = in_sizes[1];                 // B*S
    const int H    = in_sizes[0] / rows;          // 4096
    const int hv   = H / 4;                       // float4 elements per row

    refiner_kernel<<<rows, 256>>>(
        (const float4*)x, mask, (const float4*)scale, (const float4*)shift,
        alpha, (float4*)d_out, hv);
}